// round 11
// baseline (speedup 1.0000x reference)
#include <cuda_runtime.h>
#include <cuda_fp16.h>
#include <math.h>
#include <cstdint>

#define NBLK 32
#define CAP 1024
#define DK 256
#define DH 768
#define NQ 8192
#define NPART 8   /* grid.y partitions of the 32 memory blocks */

typedef uint32_t u32;

// scratch (device globals: no allocation allowed)
__device__ __half g_qh[NQ * DK];              // layernormed queries * 1/16, fp16
__device__ __half g_kh[NBLK * CAP * DK];      // keys, fp16
__device__ __half g_vth[NBLK * DK * CAP];     // values transposed [b][d][key], fp16
__device__ float  g_r[NPART * NQ * DK];       // retrieved partials per block-group
__device__ float  g_rs[NQ * DK];              // reduced retrieved values

__device__ __forceinline__ u32 packh2(float a, float b) {
    __half2 h = __floats2half2_rn(a, b);
    return *(u32*)&h;
}

// fp16 tensor-core mma, fp32 accumulate
__device__ __forceinline__ void mma_f16(float* d,
    u32 a0, u32 a1, u32 a2, u32 a3, u32 b0, u32 b1)
{
    asm("mma.sync.aligned.m16n8k16.row.col.f32.f16.f16.f32 "
        "{%0,%1,%2,%3},{%4,%5,%6,%7},{%8,%9},{%0,%1,%2,%3};"
        : "+f"(d[0]), "+f"(d[1]), "+f"(d[2]), "+f"(d[3])
        : "r"(a0), "r"(a1), "r"(a2), "r"(a3), "r"(b0), "r"(b1));
}

__device__ __forceinline__ u32 s2u(const void* p) {
    u32 a;
    asm("{ .reg .u64 t; cvta.to.shared.u64 t, %1; cvt.u32.u64 %0, t; }"
        : "=r"(a) : "l"(p));
    return a;
}
__device__ __forceinline__ void cpa16(u32 dst, const void* src) {
    asm volatile("cp.async.cg.shared.global [%0], [%1], 16;"
                 :: "r"(dst), "l"(src) : "memory");
}
#define CPA_COMMIT() asm volatile("cp.async.commit_group;" ::: "memory")
#define CPA_WAIT1()  asm volatile("cp.async.wait_group 1;" ::: "memory")

#define LDSM4(r, a) asm volatile( \
    "ldmatrix.sync.aligned.m8n8.x4.shared.b16 {%0,%1,%2,%3}, [%4];" \
    : "=r"((r)[0]), "=r"((r)[1]), "=r"((r)[2]), "=r"((r)[3]) : "r"(a))

// ---------------------------------------------------------------------------
// Kernel A: q = LayerNorm(hs @ Wk + bk) * ln_w + ln_b, scaled 1/16 -> fp16
// ---------------------------------------------------------------------------
__global__ __launch_bounds__(256) void qproj_ln_kernel(
    const float* __restrict__ hs, const float* __restrict__ Wk,
    const float* __restrict__ bk, const float* __restrict__ lnw,
    const float* __restrict__ lnb)
{
    __shared__ float As[32][16];
    __shared__ float Bs[16][256];
    const int tid = threadIdx.x;
    const int ty = tid >> 5;
    const int tx = tid & 31;
    const int m0 = blockIdx.x * 32;

    float c[4][8];
#pragma unroll
    for (int i = 0; i < 4; i++)
#pragma unroll
        for (int j = 0; j < 8; j++) c[i][j] = 0.f;

    for (int k0 = 0; k0 < DH; k0 += 16) {
        if (tid < 128) {
            int r = tid >> 2, k4 = tid & 3;
            float4 v = *(const float4*)(hs + (size_t)(m0 + r) * DH + k0 + k4 * 4);
            *(float4*)(&As[r][k4 * 4]) = v;
        }
#pragma unroll
        for (int u = 0; u < 4; u++) {
            int idx4 = tid + u * 256;
            int kk = idx4 >> 6, c4 = idx4 & 63;
            float4 v = *(const float4*)(Wk + (size_t)(k0 + kk) * DK + c4 * 4);
            *(float4*)(&Bs[kk][c4 * 4]) = v;
        }
        __syncthreads();
#pragma unroll
        for (int kk = 0; kk < 16; kk++) {
            float a[4], b[8];
#pragma unroll
            for (int i = 0; i < 4; i++) a[i] = As[ty * 4 + i][kk];
            float4 b0 = *(float4*)(&Bs[kk][tx * 8]);
            float4 b1 = *(float4*)(&Bs[kk][tx * 8 + 4]);
            b[0] = b0.x; b[1] = b0.y; b[2] = b0.z; b[3] = b0.w;
            b[4] = b1.x; b[5] = b1.y; b[6] = b1.z; b[7] = b1.w;
#pragma unroll
            for (int i = 0; i < 4; i++)
#pragma unroll
                for (int j = 0; j < 8; j++) c[i][j] += a[i] * b[j];
        }
        __syncthreads();
    }

    float bkv[8], lw[8], lb[8];
#pragma unroll
    for (int j = 0; j < 8; j++) {
        int col = tx * 8 + j;
        bkv[j] = bk[col]; lw[j] = lnw[col]; lb[j] = lnb[col];
    }
#pragma unroll
    for (int i = 0; i < 4; i++)
#pragma unroll
        for (int j = 0; j < 8; j++) c[i][j] += bkv[j];

#pragma unroll
    for (int i = 0; i < 4; i++) {
        float s = 0.f;
#pragma unroll
        for (int j = 0; j < 8; j++) s += c[i][j];
#pragma unroll
        for (int o = 16; o > 0; o >>= 1) s += __shfl_xor_sync(0xffffffffu, s, o);
        float mu = s * (1.0f / 256.0f);
        float v = 0.f;
#pragma unroll
        for (int j = 0; j < 8; j++) { float d = c[i][j] - mu; v += d * d; }
#pragma unroll
        for (int o = 16; o > 0; o >>= 1) v += __shfl_xor_sync(0xffffffffu, v, o);
        float rs = rsqrtf(v * (1.0f / 256.0f) + 1e-5f);
        float out[8];
#pragma unroll
        for (int j = 0; j < 8; j++)
            out[j] = ((c[i][j] - mu) * rs * lw[j] + lb[j]) * 0.0625f;
        __half* dst = g_qh + (size_t)(m0 + ty * 4 + i) * DK + tx * 8;
        *(uint4*)dst = make_uint4(packh2(out[0], out[1]), packh2(out[2], out[3]),
                                  packh2(out[4], out[5]), packh2(out[6], out[7]));
    }
}

// ---------------------------------------------------------------------------
// Kernel K: convert keys fp32 -> fp16
// ---------------------------------------------------------------------------
__global__ __launch_bounds__(256) void kh_kernel(const float* __restrict__ mk)
{
    size_t i = ((size_t)blockIdx.x * 256 + threadIdx.x) * 8;
    float4 v0 = *(const float4*)(mk + i);
    float4 v1 = *(const float4*)(mk + i + 4);
    *(uint4*)(g_kh + i) = make_uint4(packh2(v0.x, v0.y), packh2(v0.z, v0.w),
                                     packh2(v1.x, v1.y), packh2(v1.z, v1.w));
}

// ---------------------------------------------------------------------------
// Kernel V: transpose values per block: g_vth[b][d][key] = fp16(mv[b][key][d])
// ---------------------------------------------------------------------------
__global__ __launch_bounds__(256) void vth_kernel(const float* __restrict__ mv)
{
    __shared__ float t[32][33];
    const int b = blockIdx.z, kt = blockIdx.y, dt = blockIdx.x;
    const int r = threadIdx.x >> 3, c4 = (threadIdx.x & 7) * 4;
    float4 v = *(const float4*)(mv + ((size_t)b * CAP + kt * 32 + r) * DK + dt * 32 + c4);
    t[r][c4] = v.x; t[r][c4 + 1] = v.y; t[r][c4 + 2] = v.z; t[r][c4 + 3] = v.w;
    __syncthreads();
    uint2 o = make_uint2(packh2(t[c4][r], t[c4 + 1][r]),
                         packh2(t[c4 + 2][r], t[c4 + 3][r]));
    *(uint2*)(g_vth + ((size_t)b * DK + dt * 32 + r) * CAP + kt * 32 + c4) = o;
}

// ---------------------------------------------------------------------------
// Kernel B: per-block masked softmax attention. fp16 mma + ldmatrix,
// chunk = 32 keys, double-buffered cp.async, 128 threads (4 warps),
// TWO CTAs per SM (cross-CTA latency hiding).
// CTA = 32 queries x 4 memory blocks (grid 256 x 8).
// QK: warp w -> m16 tile (w>>1), key-half n16 (w&1); k=256.
// PV: warp w -> m16 group (w&1), col half n128 (w>>1); k=32.
// ---------------------------------------------------------------------------
#define QSTR 264
#define KSTR 264
#define VSTR 40
#define PSTR 40
#define KBUF (32 * KSTR)     /* halves per K buffer  */
#define VBUF (256 * VSTR)    /* halves per Vt buffer */
#define ATTN_SMEM (512 + 32*QSTR*2 + 2*KBUF*2 + 2*VBUF*2 + 32*PSTR*2)

extern __shared__ char sm_raw[];

__global__ void __launch_bounds__(128, 2) attn_kernel(const int* __restrict__ usage)
{
    float*  Ls  = (float*)sm_raw;                 // [32][2]
    __half* Qs  = (__half*)(sm_raw + 512);        // [32][264]
    __half* Ks  = Qs + 32 * QSTR;                 // 2 x [32][264]
    __half* Vts = Ks + 2 * KBUF;                  // 2 x [256][40]
    __half* Ps  = Vts + 2 * VBUF;                 // [32][40]

    const u32 ks_u = s2u(Ks);
    const u32 vt_u = s2u(Vts);

    const int tid  = threadIdx.x;
    const int w    = tid >> 5;
    const int lane = tid & 31;
    const int t4   = lane >> 2;
    const int tq   = lane & 3;
    const int q0   = blockIdx.x * 32;
    const int b0   = blockIdx.y * (NBLK / NPART);

    const int mw = w >> 1;          // QK m16 tile (0/1)
    const int nh = w & 1;           // QK key-half (n16)
    const int mg = w & 1;           // PV m16 tile
    const int ng = w >> 1;          // PV n128 half

    const int l15 = lane & 15, lh = lane >> 4;
    const u32 qa = s2u(Qs) + (u32)(((mw * 16 + l15) * QSTR + lh * 8) * 2);
    const u32 kb = (u32)(((nh * 16 + l15) * KSTR + lh * 8) * 2);     // + ks_u + buf
    const u32 pa = s2u(Ps) + (u32)(((mg * 16 + l15) * PSTR + lh * 8) * 2);
    const u32 vb = (u32)(((ng * 128 + l15) * VSTR + lh * 8) * 2);    // + vt_u + buf

    // Q tile -> smem (once): 32 rows x 32 segs of 16B
#pragma unroll
    for (int u = 0; u < 8; u++) {
        int idx = tid + u * 128;
        int row = idx >> 5, seg = idx & 31;
        uint4 v = *(const uint4*)(g_qh + ((size_t)(q0 + row) << 8) + seg * 8);
        *(uint4*)(Qs + row * QSTR + seg * 8) = v;
    }

    float O[16][4];
#pragma unroll
    for (int nt = 0; nt < 16; nt++)
#pragma unroll
        for (int j = 0; j < 4; j++) O[nt][j] = 0.f;

    // prefetch chunk 0 of block b0 into buffer 0
    {
        const __half* kg = g_kh + (size_t)b0 * CAP * DK;
        const __half* vg = g_vth + (size_t)b0 * DK * CAP;
#pragma unroll
        for (int u = 0; u < 8; u++) {
            int idx = tid + u * 128;
            int key = idx >> 5, seg = idx & 31;
            cpa16(ks_u + (key * KSTR + seg * 8) * 2, kg + (size_t)key * DK + seg * 8);
            int d = idx >> 2, sg = idx & 3;
            cpa16(vt_u + (d * VSTR + sg * 8) * 2, vg + (size_t)d * CAP + sg * 8);
        }
        CPA_COMMIT();
    }

    int it = 0;
    for (int bb = 0; bb < NBLK / NPART; bb++) {
        const int b = b0 + bb;
        const int use = __ldg(usage + b);
        const int nch = (use + 31) >> 5;

        float acc[16][4];
#pragma unroll
        for (int nt = 0; nt < 16; nt++)
#pragma unroll
            for (int j = 0; j < 4; j++) acc[nt][j] = 0.f;

        for (int ch = 0; ch < nch; ch++, it++) {
            const int buf = it & 1;
            const int c0 = ch * 32;

            __syncthreads();   // A: prev PV done -> buf^1 free; prev P/Ls consumed

            // prefetch next chunk (possibly next block) into buf^1
            {
                int nb = b, nc = c0 + 32;
                bool has = true;
                if (ch + 1 >= nch) {
                    if (bb + 1 < NBLK / NPART) { nb = b + 1; nc = 0; }
                    else has = false;
                }
                if (has) {
                    const int pb = buf ^ 1;
                    const __half* kg = g_kh + ((size_t)nb * CAP + nc) * DK;
                    const __half* vg = g_vth + (size_t)nb * DK * CAP + nc;
                    const u32 kd = ks_u + pb * KBUF * 2;
                    const u32 vd = vt_u + pb * VBUF * 2;
#pragma unroll
                    for (int u = 0; u < 8; u++) {
                        int idx = tid + u * 128;
                        int key = idx >> 5, seg = idx & 31;
                        cpa16(kd + (key * KSTR + seg * 8) * 2,
                              kg + (size_t)key * DK + seg * 8);
                        int d = idx >> 2, sg = idx & 3;
                        cpa16(vd + (d * VSTR + sg * 8) * 2,
                              vg + (size_t)d * CAP + sg * 8);
                    }
                }
                CPA_COMMIT();
                CPA_WAIT1();   // current chunk's group complete
            }
            __syncthreads();   // B: chunk data visible to all warps

            // ---- S = Q K^T : m16 x n16 over k=256 ----
            const u32 kbase = ks_u + buf * KBUF * 2;
            float s[2][4];
#pragma unroll
            for (int nt = 0; nt < 2; nt++)
#pragma unroll
                for (int j = 0; j < 4; j++) s[nt][j] = 0.f;
#pragma unroll
            for (int kk = 0; kk < 16; kk++) {
                u32 A[4], B[4];
                LDSM4(A, qa + kk * 32);
                LDSM4(B, kbase + kb + kk * 32);
                mma_f16(s[0], A[0], A[1], A[2], A[3], B[0], B[2]);
                mma_f16(s[1], A[0], A[1], A[2], A[3], B[1], B[3]);
            }

            // ---- mask + exp + store P + row-sum partials ----
            const int rem = use - c0;   // >= 1
            const int row = mw * 16 + t4;
            float rs_lo = 0.f, rs_hi = 0.f;
#pragma unroll
            for (int nt = 0; nt < 2; nt++) {
                int col = nh * 16 + nt * 8 + 2 * tq;
                float p0 = (col     < rem) ? __expf(s[nt][0]) : 0.f;
                float p1 = (col + 1 < rem) ? __expf(s[nt][1]) : 0.f;
                float p2 = (col     < rem) ? __expf(s[nt][2]) : 0.f;
                float p3 = (col + 1 < rem) ? __expf(s[nt][3]) : 0.f;
                rs_lo += p0 + p1;
                rs_hi += p2 + p3;
                *(u32*)(Ps + row * PSTR + col)       = packh2(p0, p1);
                *(u32*)(Ps + (row + 8) * PSTR + col) = packh2(p2, p3);
            }
            rs_lo += __shfl_xor_sync(0xffffffffu, rs_lo, 1);
            rs_lo += __shfl_xor_sync(0xffffffffu, rs_lo, 2);
            rs_hi += __shfl_xor_sync(0xffffffffu, rs_hi, 1);
            rs_hi += __shfl_xor_sync(0xffffffffu, rs_hi, 2);
            if (tq == 0) {   // unique writer per (row, key-half)
                if (ch == 0) {
                    Ls[row * 2 + nh]       = rs_lo;
                    Ls[(row + 8) * 2 + nh] = rs_hi;
                } else {
                    Ls[row * 2 + nh]       += rs_lo;
                    Ls[(row + 8) * 2 + nh] += rs_hi;
                }
            }
            __syncthreads();   // C: P + Ls visible

            // ---- acc += P @ V : m16 x n128 over k=32 ----
            const u32 vbase = vt_u + buf * VBUF * 2;
#pragma unroll
            for (int kk = 0; kk < 2; kk++) {
                u32 A[4];
                LDSM4(A, pa + kk * 32);
#pragma unroll
                for (int nt = 0; nt < 8; nt++) {
                    u32 B[4];
                    LDSM4(B, vbase + vb + nt * 16 * VSTR * 2 + kk * 32);
                    mma_f16(acc[2 * nt],     A[0], A[1], A[2], A[3], B[0], B[2]);
                    mma_f16(acc[2 * nt + 1], A[0], A[1], A[2], A[3], B[1], B[3]);
                }
            }
        }

        // ---- finalize block: O += acc / rowsum ----
        __syncthreads();   // last chunk's Ls writes visible
        {
            const int r = mg * 16 + t4;
            float il = 1.0f / (Ls[r * 2] + Ls[r * 2 + 1]);
            float ih = 1.0f / (Ls[(r + 8) * 2] + Ls[(r + 8) * 2 + 1]);
#pragma unroll
            for (int nt = 0; nt < 16; nt++) {
                O[nt][0] += acc[nt][0] * il;
                O[nt][1] += acc[nt][1] * il;
                O[nt][2] += acc[nt][2] * ih;
                O[nt][3] += acc[nt][3] * ih;
            }
        }
    }

    // write partial retrieved values for this block group
    float* dst = g_r + (size_t)blockIdx.y * NQ * DK;
    {
        int r = q0 + mg * 16 + t4;
#pragma unroll
        for (int nt = 0; nt < 8; nt++) {
#pragma unroll
            for (int h = 0; h < 2; h++) {
                int col = ng * 128 + nt * 16 + h * 8 + 2 * tq;
                *(float2*)(dst + (size_t)r * DK + col) =
                    make_float2(O[2 * nt + h][0], O[2 * nt + h][1]);
                *(float2*)(dst + (size_t)(r + 8) * DK + col) =
                    make_float2(O[2 * nt + h][2], O[2 * nt + h][3]);
            }
        }
    }
}

// ---------------------------------------------------------------------------
// Kernel R: reduce NPART partials -> g_rs
// ---------------------------------------------------------------------------
__global__ __launch_bounds__(256) void reduce_r_kernel()
{
    size_t i = ((size_t)blockIdx.x * 256 + threadIdx.x) * 4;
    float4 a = *(const float4*)(g_r + i);
#pragma unroll
    for (int p = 1; p < NPART; p++) {
        float4 b = *(const float4*)(g_r + (size_t)p * NQ * DK + i);
        a.x += b.x; a.y += b.y; a.z += b.z; a.w += b.w;
    }
    *(float4*)(g_rs + i) = a;
}

// ---------------------------------------------------------------------------
// Kernel C: out = g_rs @ Wo + bo      [8192,256]x[256,768]
// ---------------------------------------------------------------------------
__global__ __launch_bounds__(256) void out_gemm_kernel(
    const float* __restrict__ Wo, const float* __restrict__ bo,
    float* __restrict__ out)
{
    __shared__ float As[64][20];
    __shared__ float Bs[16][64];
    const int tid = threadIdx.x;
    const int ty = tid >> 4;
    const int tx = tid & 15;
    const int m0 = blockIdx.x * 64;
    const int n0 = blockIdx.y * 64;

    float c[4][4];
#pragma unroll
    for (int i = 0; i < 4; i++)
#pragma unroll
        for (int j = 0; j < 4; j++) c[i][j] = 0.f;

    for (int k0 = 0; k0 < DK; k0 += 16) {
        {
            int r = tid >> 2, k4 = tid & 3;
            float4 v = *(const float4*)(g_rs + (size_t)(m0 + r) * DK + k0 + k4 * 4);
            *(float4*)(&As[r][k4 * 4]) = v;
        }
        {
            int kk = tid >> 4, c4 = tid & 15;
            float4 v = *(const float4*)(Wo + (size_t)(k0 + kk) * DH + n0 + c4 * 4);
            *(float4*)(&Bs[kk][c4 * 4]) = v;
        }
        __syncthreads();
#pragma unroll
        for (int kk = 0; kk < 16; kk++) {
            float a[4];
#pragma unroll
            for (int i = 0; i < 4; i++) a[i] = As[ty * 4 + i][kk];
            float4 bv = *(float4*)(&Bs[kk][tx * 4]);
            float b[4] = {bv.x, bv.y, bv.z, bv.w};
#pragma unroll
            for (int i = 0; i < 4; i++)
#pragma unroll
                for (int j = 0; j < 4; j++) c[i][j] += a[i] * b[j];
        }
        __syncthreads();
    }

    float4 bv = *(const float4*)(bo + n0 + tx * 4);
    float bb[4] = {bv.x, bv.y, bv.z, bv.w};
#pragma unroll
    for (int i = 0; i < 4; i++) {
        float4 r = make_float4(c[i][0] + bb[0], c[i][1] + bb[1],
                               c[i][2] + bb[2], c[i][3] + bb[3]);
        *(float4*)(out + (size_t)(m0 + ty * 4 + i) * DH + n0 + tx * 4) = r;
    }
}

// ---------------------------------------------------------------------------
extern "C" void kernel_launch(void* const* d_in, const int* in_sizes, int n_in,
                              void* d_out, int out_size)
{
    const float* hs  = (const float*)d_in[0];
    const float* Wk  = (const float*)d_in[1];
    const float* bk  = (const float*)d_in[2];
    const float* lnw = (const float*)d_in[3];
    const float* lnb = (const float*)d_in[4];
    const float* mk  = (const float*)d_in[5];
    const float* mv  = (const float*)d_in[6];
    const float* Wo  = (const float*)d_in[7];
    const float* bo  = (const float*)d_in[8];
    const int* usage = (const int*)d_in[9];
    float* out = (float*)d_out;

    cudaFuncSetAttribute(attn_kernel, cudaFuncAttributeMaxDynamicSharedMemorySize,
                         ATTN_SMEM);

    qproj_ln_kernel<<<NQ / 32, 256>>>(hs, Wk, bk, lnw, lnb);
    kh_kernel<<<(NBLK * CAP * DK) / (256 * 8), 256>>>(mk);
    vth_kernel<<<dim3(DK / 32, CAP / 32, NBLK), 256>>>(mv);
    attn_kernel<<<dim3(NQ / 32, NPART), 128, ATTN_SMEM>>>(usage);
    reduce_r_kernel<<<(NQ * DK) / (256 * 4), 256>>>();
    dim3 gc(NQ / 64, DH / 64);
    out_gemm_kernel<<<gc, 256>>>(Wo, bo, out);
}

// round 12
// speedup vs baseline: 1.1395x; 1.1395x over previous
#include <cuda_runtime.h>
#include <cuda_fp16.h>
#include <math.h>
#include <cstdint>

#define NBLK 32
#define CAP 1024
#define DK 256
#define DH 768
#define NQ 8192
#define NPART 8                 /* grid.y partitions of the 32 memory blocks */
#define NBPC (NBLK / NPART)     /* blocks per CTA = 4 */

typedef uint32_t u32;

// scratch (device globals: no allocation allowed)
__device__ __half g_qh[NQ * DK];              // layernormed queries * 1/16, fp16
__device__ __half g_kh[NBLK * CAP * DK];      // keys, fp16
__device__ __half g_vth[NBLK * DK * CAP];     // values transposed [b][d][key], fp16
__device__ float  g_r[NPART * NQ * DK];       // retrieved partials per block-group
__device__ float  g_rs[NQ * DK];              // reduced retrieved values

__device__ __forceinline__ u32 packh2(float a, float b) {
    __half2 h = __floats2half2_rn(a, b);
    return *(u32*)&h;
}

__device__ __forceinline__ void mma_f16(float* d,
    u32 a0, u32 a1, u32 a2, u32 a3, u32 b0, u32 b1)
{
    asm("mma.sync.aligned.m16n8k16.row.col.f32.f16.f16.f32 "
        "{%0,%1,%2,%3},{%4,%5,%6,%7},{%8,%9},{%0,%1,%2,%3};"
        : "+f"(d[0]), "+f"(d[1]), "+f"(d[2]), "+f"(d[3])
        : "r"(a0), "r"(a1), "r"(a2), "r"(a3), "r"(b0), "r"(b1));
}

__device__ __forceinline__ u32 s2u(const void* p) {
    u32 a;
    asm("{ .reg .u64 t; cvta.to.shared.u64 t, %1; cvt.u32.u64 %0, t; }"
        : "=r"(a) : "l"(p));
    return a;
}
__device__ __forceinline__ void cpa16(u32 dst, const void* src) {
    asm volatile("cp.async.cg.shared.global [%0], [%1], 16;"
                 :: "r"(dst), "l"(src) : "memory");
}
#define CPA_COMMIT() asm volatile("cp.async.commit_group;" ::: "memory")
#define CPA_WAIT1()  asm volatile("cp.async.wait_group 1;" ::: "memory")
#define CPA_WAIT0()  asm volatile("cp.async.wait_group 0;" ::: "memory")

#define LDSM4(r, a) asm volatile( \
    "ldmatrix.sync.aligned.m8n8.x4.shared.b16 {%0,%1,%2,%3}, [%4];" \
    : "=r"((r)[0]), "=r"((r)[1]), "=r"((r)[2]), "=r"((r)[3]) : "r"(a))

// ---------------------------------------------------------------------------
// Kernel A: q = LayerNorm(hs @ Wk + bk) * ln_w + ln_b, scaled 1/16 -> fp16
// ---------------------------------------------------------------------------
__global__ __launch_bounds__(256) void qproj_ln_kernel(
    const float* __restrict__ hs, const float* __restrict__ Wk,
    const float* __restrict__ bk, const float* __restrict__ lnw,
    const float* __restrict__ lnb)
{
    __shared__ float As[32][16];
    __shared__ float Bs[16][256];
    const int tid = threadIdx.x;
    const int ty = tid >> 5;
    const int tx = tid & 31;
    const int m0 = blockIdx.x * 32;

    float c[4][8];
#pragma unroll
    for (int i = 0; i < 4; i++)
#pragma unroll
        for (int j = 0; j < 8; j++) c[i][j] = 0.f;

    for (int k0 = 0; k0 < DH; k0 += 16) {
        if (tid < 128) {
            int r = tid >> 2, k4 = tid & 3;
            float4 v = *(const float4*)(hs + (size_t)(m0 + r) * DH + k0 + k4 * 4);
            *(float4*)(&As[r][k4 * 4]) = v;
        }
#pragma unroll
        for (int u = 0; u < 4; u++) {
            int idx4 = tid + u * 256;
            int kk = idx4 >> 6, c4 = idx4 & 63;
            float4 v = *(const float4*)(Wk + (size_t)(k0 + kk) * DK + c4 * 4);
            *(float4*)(&Bs[kk][c4 * 4]) = v;
        }
        __syncthreads();
#pragma unroll
        for (int kk = 0; kk < 16; kk++) {
            float a[4], b[8];
#pragma unroll
            for (int i = 0; i < 4; i++) a[i] = As[ty * 4 + i][kk];
            float4 b0 = *(float4*)(&Bs[kk][tx * 8]);
            float4 b1 = *(float4*)(&Bs[kk][tx * 8 + 4]);
            b[0] = b0.x; b[1] = b0.y; b[2] = b0.z; b[3] = b0.w;
            b[4] = b1.x; b[5] = b1.y; b[6] = b1.z; b[7] = b1.w;
#pragma unroll
            for (int i = 0; i < 4; i++)
#pragma unroll
                for (int j = 0; j < 8; j++) c[i][j] += a[i] * b[j];
        }
        __syncthreads();
    }

    float bkv[8], lw[8], lb[8];
#pragma unroll
    for (int j = 0; j < 8; j++) {
        int col = tx * 8 + j;
        bkv[j] = bk[col]; lw[j] = lnw[col]; lb[j] = lnb[col];
    }
#pragma unroll
    for (int i = 0; i < 4; i++)
#pragma unroll
        for (int j = 0; j < 8; j++) c[i][j] += bkv[j];

#pragma unroll
    for (int i = 0; i < 4; i++) {
        float s = 0.f;
#pragma unroll
        for (int j = 0; j < 8; j++) s += c[i][j];
#pragma unroll
        for (int o = 16; o > 0; o >>= 1) s += __shfl_xor_sync(0xffffffffu, s, o);
        float mu = s * (1.0f / 256.0f);
        float v = 0.f;
#pragma unroll
        for (int j = 0; j < 8; j++) { float d = c[i][j] - mu; v += d * d; }
#pragma unroll
        for (int o = 16; o > 0; o >>= 1) v += __shfl_xor_sync(0xffffffffu, v, o);
        float rs = rsqrtf(v * (1.0f / 256.0f) + 1e-5f);
        float out[8];
#pragma unroll
        for (int j = 0; j < 8; j++)
            out[j] = ((c[i][j] - mu) * rs * lw[j] + lb[j]) * 0.0625f;
        __half* dst = g_qh + (size_t)(m0 + ty * 4 + i) * DK + tx * 8;
        *(uint4*)dst = make_uint4(packh2(out[0], out[1]), packh2(out[2], out[3]),
                                  packh2(out[4], out[5]), packh2(out[6], out[7]));
    }
}

// ---------------------------------------------------------------------------
// Kernel K: convert keys fp32 -> fp16
// ---------------------------------------------------------------------------
__global__ __launch_bounds__(256) void kh_kernel(const float* __restrict__ mk)
{
    size_t i = ((size_t)blockIdx.x * 256 + threadIdx.x) * 8;
    float4 v0 = *(const float4*)(mk + i);
    float4 v1 = *(const float4*)(mk + i + 4);
    *(uint4*)(g_kh + i) = make_uint4(packh2(v0.x, v0.y), packh2(v0.z, v0.w),
                                     packh2(v1.x, v1.y), packh2(v1.z, v1.w));
}

// ---------------------------------------------------------------------------
// Kernel V: transpose values per block: g_vth[b][d][key] = fp16(mv[b][key][d])
// ---------------------------------------------------------------------------
__global__ __launch_bounds__(256) void vth_kernel(const float* __restrict__ mv)
{
    __shared__ float t[32][33];
    const int b = blockIdx.z, kt = blockIdx.y, dt = blockIdx.x;
    const int r = threadIdx.x >> 3, c4 = (threadIdx.x & 7) * 4;
    float4 v = *(const float4*)(mv + ((size_t)b * CAP + kt * 32 + r) * DK + dt * 32 + c4);
    t[r][c4] = v.x; t[r][c4 + 1] = v.y; t[r][c4 + 2] = v.z; t[r][c4 + 3] = v.w;
    __syncthreads();
    uint2 o = make_uint2(packh2(t[c4][r], t[c4 + 1][r]),
                         packh2(t[c4 + 2][r], t[c4 + 3][r]));
    *(uint2*)(g_vth + ((size_t)b * DK + dt * 32 + r) * CAP + kt * 32 + c4) = o;
}

// ---------------------------------------------------------------------------
// Kernel B: per-block masked softmax attention, software-pipelined:
// PV(chunk i) and QK(chunk i+1) share one instruction stream (independent
// chains -> 2x ILP). chunk = 32 keys; K/V triple-buffered (prefetch +2),
// P double-buffered, Ls double-buffered by block parity. One barrier +
// one cp.async wait per chunk.
// CTA = 64 queries x 4 memory blocks (grid 128 x 8), 256 threads.
// QK: warp w -> m16 (w>>1), key-half n16 (w&1); k=256.
// PV: warp w -> m32 (w&1), col group n64 (w>>1); k=32.
// ---------------------------------------------------------------------------
#define QSTR 264
#define KSTR 264
#define VSTR 40
#define PSTR 40
#define KBUF (32 * KSTR)      /* halves per K buffer  */
#define VBUF (256 * VSTR)     /* halves per Vt buffer */
#define PBUF (64 * PSTR)      /* halves per P buffer  */
#define ATTN_SMEM (1024 + (64*QSTR + 3*KBUF + 3*VBUF + 2*PBUF) * 2)

extern __shared__ char sm_raw[];

__global__ __launch_bounds__(256, 1) void attn_kernel(const int* __restrict__ usage)
{
    float*  Ls  = (float*)sm_raw;                  // [2 parity][64][2]
    __half* Qs  = (__half*)(sm_raw + 1024);        // [64][264]
    __half* Ks  = Qs + 64 * QSTR;                  // 3 x [32][264]
    __half* Vts = Ks + 3 * KBUF;                   // 3 x [256][40]
    __half* Ps  = Vts + 3 * VBUF;                  // 2 x [64][40]

    const u32 ks_u = s2u(Ks);
    const u32 vt_u = s2u(Vts);
    const u32 ps_u = s2u(Ps);

    const int tid  = threadIdx.x;
    const int w    = tid >> 5;
    const int lane = tid & 31;
    const int t4   = lane >> 2;
    const int tq   = lane & 3;
    const int q0   = blockIdx.x * 64;
    const int b0   = blockIdx.y * NBPC;

    const int mw = w >> 1;          // QK m16 tile (0..3)
    const int nh = w & 1;           // QK key-half (n16)
    const int mg = w & 1;           // PV m32 group
    const int ng = w >> 1;          // PV n64 group (0..3)

    const int l15 = lane & 15, lh = lane >> 4;
    const u32 qa  = s2u(Qs) + (u32)(((mw * 16 + l15) * QSTR + lh * 8) * 2);
    const u32 kbo = (u32)(((nh * 16 + l15) * KSTR + lh * 8) * 2);
    const u32 pao = (u32)(((mg * 32 + l15) * PSTR + lh * 8) * 2);
    const u32 vbo = (u32)(((ng * 64 + l15) * VSTR + lh * 8) * 2);

    // Q tile -> smem (once)
#pragma unroll
    for (int u = 0; u < 8; u++) {
        int idx = tid + u * 256;
        int row = idx >> 5, seg = idx & 31;
        uint4 v = *(const uint4*)(g_qh + ((size_t)(q0 + row) << 8) + seg * 8);
        *(uint4*)(Qs + row * QSTR + seg * 8) = v;
    }

    float O[2][8][4], acc[2][8][4];
#pragma unroll
    for (int mt = 0; mt < 2; mt++)
#pragma unroll
        for (int nt = 0; nt < 8; nt++)
#pragma unroll
            for (int j = 0; j < 4; j++) { O[mt][nt][j] = 0.f; acc[mt][nt][j] = 0.f; }

    // prefetch: 4 K-cpa16 + 4 V-cpa16 per thread per 32-key chunk
#define PREFETCH(b_, c_, buf_) do {                                            \
        const __half* kg_ = g_kh + ((size_t)(b0 + (b_)) * CAP + (c_) * 32) * DK; \
        const __half* vg_ = g_vth + (size_t)(b0 + (b_)) * DK * CAP + (c_) * 32;  \
        const u32 kd_ = ks_u + (buf_) * KBUF * 2;                               \
        const u32 vd_ = vt_u + (buf_) * VBUF * 2;                               \
        _Pragma("unroll")                                                       \
        for (int u_ = 0; u_ < 4; u_++) {                                        \
            int idx_ = tid + u_ * 256;                                          \
            int key_ = idx_ >> 5, seg_ = idx_ & 31;                             \
            cpa16(kd_ + (key_ * KSTR + seg_ * 8) * 2,                           \
                  kg_ + (size_t)key_ * DK + seg_ * 8);                          \
            int d_ = idx_ >> 2, sg_ = idx_ & 3;                                 \
            cpa16(vd_ + (d_ * VSTR + sg_ * 8) * 2,                              \
                  vg_ + (size_t)d_ * CAP + sg_ * 8);                            \
        }                                                                       \
    } while (0)

#define ADVC(b_, c_, u_) do {                                                   \
        if (++(c_) >= (((u_) + 31) >> 5)) {                                     \
            (c_) = 0;                                                           \
            if (++(b_) < NBPC) (u_) = __ldg(usage + b0 + (b_));                 \
        }                                                                       \
    } while (0)

    // QK of chunk in buffer buf -> sd[2][4]
#define QK_STEP(buf_, sd_) do {                                                 \
        const u32 kb_ = ks_u + (buf_) * KBUF * 2 + kbo;                         \
        _Pragma("unroll")                                                       \
        for (int kk_ = 0; kk_ < 16; kk_++) {                                    \
            u32 A_[4], B_[4];                                                   \
            LDSM4(A_, qa + kk_ * 32);                                           \
            LDSM4(B_, kb_ + kk_ * 32);                                          \
            mma_f16(sd_[0], A_[0], A_[1], A_[2], A_[3], B_[0], B_[2]);          \
            mma_f16(sd_[1], A_[0], A_[1], A_[2], A_[3], B_[1], B_[3]);          \
        }                                                                       \
    } while (0)

    // PV of chunk in buffer buf with P buffer pbuf -> acc
#define PV_STEP(buf_, pbuf_) do {                                               \
        const u32 vb_ = vt_u + (buf_) * VBUF * 2 + vbo;                         \
        const u32 pb_ = ps_u + (pbuf_) * PBUF * 2 + pao;                        \
        _Pragma("unroll")                                                       \
        for (int kk_ = 0; kk_ < 2; kk_++) {                                     \
            u32 A0_[4], A1_[4];                                                 \
            LDSM4(A0_, pb_ + kk_ * 32);                                         \
            LDSM4(A1_, pb_ + 16 * PSTR * 2 + kk_ * 32);                         \
            _Pragma("unroll")                                                   \
            for (int nt_ = 0; nt_ < 4; nt_++) {                                 \
                u32 B_[4];                                                      \
                LDSM4(B_, vb_ + nt_ * 16 * VSTR * 2 + kk_ * 32);                \
                mma_f16(acc[0][2 * nt_],     A0_[0], A0_[1], A0_[2], A0_[3], B_[0], B_[2]); \
                mma_f16(acc[0][2 * nt_ + 1], A0_[0], A0_[1], A0_[2], A0_[3], B_[1], B_[3]); \
                mma_f16(acc[1][2 * nt_],     A1_[0], A1_[1], A1_[2], A1_[3], B_[0], B_[2]); \
                mma_f16(acc[1][2 * nt_ + 1], A1_[0], A1_[1], A1_[2], A1_[3], B_[1], B_[3]); \
            }                                                                   \
        }                                                                       \
    } while (0)

    // softmax of current chunk (scores sd) -> P[pbuf], Ls[par]
#define SOFTMAX_STEP(sd_, pbuf_, par_, rem_, first_) do {                       \
        const int row_ = mw * 16 + t4;                                          \
        __half* pp_ = Ps + (pbuf_) * PBUF;                                      \
        float rl_ = 0.f, rh_ = 0.f;                                             \
        _Pragma("unroll")                                                       \
        for (int nt_ = 0; nt_ < 2; nt_++) {                                     \
            int col_ = nh * 16 + nt_ * 8 + 2 * tq;                              \
            float p0_ = (col_     < (rem_)) ? __expf(sd_[nt_][0]) : 0.f;        \
            float p1_ = (col_ + 1 < (rem_)) ? __expf(sd_[nt_][1]) : 0.f;        \
            float p2_ = (col_     < (rem_)) ? __expf(sd_[nt_][2]) : 0.f;        \
            float p3_ = (col_ + 1 < (rem_)) ? __expf(sd_[nt_][3]) : 0.f;        \
            rl_ += p0_ + p1_; rh_ += p2_ + p3_;                                 \
            *(u32*)(pp_ + row_ * PSTR + col_)       = packh2(p0_, p1_);         \
            *(u32*)(pp_ + (row_ + 8) * PSTR + col_) = packh2(p2_, p3_);         \
        }                                                                       \
        rl_ += __shfl_xor_sync(0xffffffffu, rl_, 1);                            \
        rl_ += __shfl_xor_sync(0xffffffffu, rl_, 2);                            \
        rh_ += __shfl_xor_sync(0xffffffffu, rh_, 1);                            \
        rh_ += __shfl_xor_sync(0xffffffffu, rh_, 2);                            \
        if (tq == 0) {                                                          \
            float* lp_ = Ls + (par_) * 128;                                     \
            if (first_) {                                                       \
                lp_[row_ * 2 + nh]       = rl_;                                 \
                lp_[(row_ + 8) * 2 + nh] = rh_;                                 \
            } else {                                                            \
                lp_[row_ * 2 + nh]       += rl_;                                \
                lp_[(row_ + 8) * 2 + nh] += rh_;                                \
            }                                                                   \
        }                                                                       \
    } while (0)

#define FINALIZE(par_) do {                                                     \
        const float* lp_ = Ls + (par_) * 128;                                   \
        _Pragma("unroll")                                                       \
        for (int mt_ = 0; mt_ < 2; mt_++) {                                     \
            int r_ = mg * 32 + mt_ * 16 + t4;                                   \
            float il_ = 1.0f / (lp_[r_ * 2] + lp_[r_ * 2 + 1]);                 \
            float ih_ = 1.0f / (lp_[(r_ + 8) * 2] + lp_[(r_ + 8) * 2 + 1]);     \
            _Pragma("unroll")                                                   \
            for (int nt_ = 0; nt_ < 8; nt_++) {                                 \
                O[mt_][nt_][0] += acc[mt_][nt_][0] * il_;                       \
                O[mt_][nt_][1] += acc[mt_][nt_][1] * il_;                       \
                O[mt_][nt_][2] += acc[mt_][nt_][2] * ih_;                       \
                O[mt_][nt_][3] += acc[mt_][nt_][3] * ih_;                       \
                acc[mt_][nt_][0] = 0.f; acc[mt_][nt_][1] = 0.f;                 \
                acc[mt_][nt_][2] = 0.f; acc[mt_][nt_][3] = 0.f;                 \
            }                                                                   \
        }                                                                       \
    } while (0)

    // chunk cursors: cur (softmax/PV), nxt (QK), pf (prefetch, +2)
    int cb = 0, cc = 0, cu = __ldg(usage + b0);
    int nb = cb, nc = cc, nu = cu; ADVC(nb, nc, nu);
    int pb = nb, pc = nc, pu = nu; ADVC(pb, pc, pu);

    float s[2][4], ns[2][4];
#pragma unroll
    for (int nt = 0; nt < 2; nt++)
#pragma unroll
        for (int j = 0; j < 4; j++) { s[nt][j] = 0.f; ns[nt][j] = 0.f; }

    // pre-loop: prefetch chunk0 -> buf0, chunk1 -> buf1 (>=4 chunks always)
    PREFETCH(cb, cc, 0); CPA_COMMIT();
    PREFETCH(nb, nc, 1); CPA_COMMIT();
    CPA_WAIT1();            // chunk0 ready
    __syncthreads();        // chunk0 + Q visible
    QK_STEP(0, s);          // S(chunk0)

    int it = 0;
    while (nb < NBPC) {     // current chunk has a successor
        // 1) softmax cur -> Ps[it&1], Ls[cb&1]
        SOFTMAX_STEP(s, it & 1, cb & 1, cu - cc * 32, cc == 0);
        // 2) chunk it+1 loads complete (issued >=1 full iteration ago)
        CPA_WAIT0();
        // 3) one barrier: P/Ls visible; chunk it+1 visible; all warps done
        //    reading K(it) [QK last iter] and V(it-1) [PV last iter], so
        //    buffer (it+2)%3 (holding chunk it-1) is free for prefetch.
        __syncthreads();
        // 4) prefetch chunk it+2
        if (pb < NBPC) { PREFETCH(pb, pc, (it + 2) % 3); ADVC(pb, pc, pu); }
        CPA_COMMIT();
        // 5) fused mma step: QK(it+1) -> ns  ||  PV(it) -> acc (independent)
#pragma unroll
        for (int nt = 0; nt < 2; nt++)
#pragma unroll
            for (int j = 0; j < 4; j++) ns[nt][j] = 0.f;
        QK_STEP((it + 1) % 3, ns);
        PV_STEP(it % 3, it & 1);
        // 6) block boundary: fold acc into O
        if (cc == ((cu + 31) >> 5) - 1) FINALIZE(cb & 1);
        // advance cursors; S <- nS
        cb = nb; cc = nc; cu = nu; ADVC(nb, nc, nu);
#pragma unroll
        for (int nt = 0; nt < 2; nt++)
#pragma unroll
            for (int j = 0; j < 4; j++) s[nt][j] = ns[nt][j];
        ++it;
    }

    // epilogue: last chunk (no successor)
    SOFTMAX_STEP(s, it & 1, cb & 1, cu - cc * 32, cc == 0);
    __syncthreads();
    PV_STEP(it % 3, it & 1);
    FINALIZE(cb & 1);

    // write partial retrieved values for this block group
    float* dst = g_r + (size_t)blockIdx.y * NQ * DK;
#pragma unroll
    for (int mt = 0; mt < 2; mt++) {
        int r = q0 + mg * 32 + mt * 16 + t4;
#pragma unroll
        for (int nt = 0; nt < 8; nt++) {
            int col = ng * 64 + nt * 8 + 2 * tq;
            *(float2*)(dst + (size_t)r * DK + col) =
                make_float2(O[mt][nt][0], O[mt][nt][1]);
            *(float2*)(dst + (size_t)(r + 8) * DK + col) =
                make_float2(O[mt][nt][2], O[mt][nt][3]);
        }
    }
}

// ---------------------------------------------------------------------------
// Kernel R: reduce NPART partials -> g_rs
// ---------------------------------------------------------------------------
__global__ __launch_bounds__(256) void reduce_r_kernel()
{
    size_t i = ((size_t)blockIdx.x * 256 + threadIdx.x) * 4;
    float4 a = *(const float4*)(g_r + i);
#pragma unroll
    for (int p = 1; p < NPART; p++) {
        float4 b = *(const float4*)(g_r + (size_t)p * NQ * DK + i);
        a.x += b.x; a.y += b.y; a.z += b.z; a.w += b.w;
    }
    *(float4*)(g_rs + i) = a;
}

// ---------------------------------------------------------------------------
// Kernel C: out = g_rs @ Wo + bo      [8192,256]x[256,768]
// ---------------------------------------------------------------------------
__global__ __launch_bounds__(256) void out_gemm_kernel(
    const float* __restrict__ Wo, const float* __restrict__ bo,
    float* __restrict__ out)
{
    __shared__ float As[64][20];
    __shared__ float Bs[16][64];
    const int tid = threadIdx.x;
    const int ty = tid >> 4;
    const int tx = tid & 15;
    const int m0 = blockIdx.x * 64;
    const int n0 = blockIdx.y * 64;

    float c[4][4];
#pragma unroll
    for (int i = 0; i < 4; i++)
#pragma unroll
        for (int j = 0; j < 4; j++) c[i][j] = 0.f;

    for (int k0 = 0; k0 < DK; k0 += 16) {
        {
            int r = tid >> 2, k4 = tid & 3;
            float4 v = *(const float4*)(g_rs + (size_t)(m0 + r) * DK + k0 + k4 * 4);
            *(float4*)(&As[r][k4 * 4]) = v;
        }
        {
            int kk = tid >> 4, c4 = tid & 15;
            float4 v = *(const float4*)(Wo + (size_t)(k0 + kk) * DH + n0 + c4 * 4);
            *(float4*)(&Bs[kk][c4 * 4]) = v;
        }
        __syncthreads();
#pragma unroll
        for (int kk = 0; kk < 16; kk++) {
            float a[4];
#pragma unroll
            for (int i = 0; i < 4; i++) a[i] = As[ty * 4 + i][kk];
            float4 bv = *(float4*)(&Bs[kk][tx * 4]);
            float b[4] = {bv.x, bv.y, bv.z, bv.w};
#pragma unroll
            for (int i = 0; i < 4; i++)
#pragma unroll
                for (int j = 0; j < 4; j++) c[i][j] += a[i] * b[j];
        }
        __syncthreads();
    }

    float4 bv = *(const float4*)(bo + n0 + tx * 4);
    float bb[4] = {bv.x, bv.y, bv.z, bv.w};
#pragma unroll
    for (int i = 0; i < 4; i++) {
        float4 r = make_float4(c[i][0] + bb[0], c[i][1] + bb[1],
                               c[i][2] + bb[2], c[i][3] + bb[3]);
        *(float4*)(out + (size_t)(m0 + ty * 4 + i) * DH + n0 + tx * 4) = r;
    }
}

// ---------------------------------------------------------------------------
extern "C" void kernel_launch(void* const* d_in, const int* in_sizes, int n_in,
                              void* d_out, int out_size)
{
    const float* hs  = (const float*)d_in[0];
    const float* Wk  = (const float*)d_in[1];
    const float* bk  = (const float*)d_in[2];
    const float* lnw = (const float*)d_in[3];
    const float* lnb = (const float*)d_in[4];
    const float* mk  = (const float*)d_in[5];
    const float* mv  = (const float*)d_in[6];
    const float* Wo  = (const float*)d_in[7];
    const float* bo  = (const float*)d_in[8];
    const int* usage = (const int*)d_in[9];
    float* out = (float*)d_out;

    cudaFuncSetAttribute(attn_kernel, cudaFuncAttributeMaxDynamicSharedMemorySize,
                         ATTN_SMEM);

    qproj_ln_kernel<<<NQ / 32, 256>>>(hs, Wk, bk, lnw, lnb);
    kh_kernel<<<(NBLK * CAP * DK) / (256 * 8), 256>>>(mk);
    vth_kernel<<<dim3(DK / 32, CAP / 32, NBLK), 256>>>(mv);
    attn_kernel<<<dim3(NQ / 64, NPART), 256, ATTN_SMEM>>>(usage);
    reduce_r_kernel<<<(NQ * DK) / (256 * 4), 256>>>();
    dim3 gc(NQ / 64, DH / 64);
    out_gemm_kernel<<<gc, 256>>>(Wo, bo, out);
}

// round 13
// speedup vs baseline: 1.2451x; 1.0926x over previous
#include <cuda_runtime.h>
#include <cuda_fp16.h>
#include <math.h>
#include <cstdint>

#define NBLK 32
#define CAP 1024
#define DK 256
#define DH 768
#define NQ 8192
#define NPART 8   /* grid.y partitions of the 32 memory blocks */

typedef uint32_t u32;
typedef unsigned long long ull;

// scratch (device globals: no allocation allowed)
__device__ __half g_qh[NQ * DK];              // layernormed queries * 1/16, fp16
__device__ __half g_kh[NBLK * CAP * DK];      // keys, fp16
__device__ __half g_vth[NBLK * DK * CAP];     // values transposed [b][d][key], fp16
__device__ float  g_r[NPART * NQ * DK];       // retrieved partials per block-group
__device__ float  g_rs[NQ * DK];              // reduced retrieved values

__device__ __forceinline__ u32 packh2(float a, float b) {
    __half2 h = __floats2half2_rn(a, b);
    return *(u32*)&h;
}

// packed dual-fp32 FMA: d = a*b + d (exact fp32, 2 lanes per issue)
__device__ __forceinline__ void fma2(ull& d, ull a, ull b) {
    asm("fma.rn.f32x2 %0, %1, %2, %0;" : "+l"(d) : "l"(a), "l"(b));
}
__device__ __forceinline__ ull dup2(float a) {
    ull r; asm("mov.b64 %0, {%1, %1};" : "=l"(r) : "f"(a)); return r;
}

// fp16 tensor-core mma, fp32 accumulate
__device__ __forceinline__ void mma_f16(float* d,
    u32 a0, u32 a1, u32 a2, u32 a3, u32 b0, u32 b1)
{
    asm("mma.sync.aligned.m16n8k16.row.col.f32.f16.f16.f32 "
        "{%0,%1,%2,%3},{%4,%5,%6,%7},{%8,%9},{%0,%1,%2,%3};"
        : "+f"(d[0]), "+f"(d[1]), "+f"(d[2]), "+f"(d[3])
        : "r"(a0), "r"(a1), "r"(a2), "r"(a3), "r"(b0), "r"(b1));
}

__device__ __forceinline__ u32 s2u(const void* p) {
    u32 a;
    asm("{ .reg .u64 t; cvta.to.shared.u64 t, %1; cvt.u32.u64 %0, t; }"
        : "=r"(a) : "l"(p));
    return a;
}
__device__ __forceinline__ void cpa16(u32 dst, const void* src) {
    asm volatile("cp.async.cg.shared.global [%0], [%1], 16;"
                 :: "r"(dst), "l"(src) : "memory");
}
#define CPA_COMMIT() asm volatile("cp.async.commit_group;" ::: "memory")
#define CPA_WAIT1()  asm volatile("cp.async.wait_group 1;" ::: "memory")

#define LDSM4(r, a) asm volatile( \
    "ldmatrix.sync.aligned.m8n8.x4.shared.b16 {%0,%1,%2,%3}, [%4];" \
    : "=r"((r)[0]), "=r"((r)[1]), "=r"((r)[2]), "=r"((r)[3]) : "r"(a))

// ---------------------------------------------------------------------------
// Kernel A: q = LayerNorm(hs @ Wk + bk) * ln_w + ln_b, scaled 1/16 -> fp16
// BM=32 (256 CTAs), 256 threads, f32x2 packed FMA (fma-issue-bound kernel).
// ---------------------------------------------------------------------------
__global__ __launch_bounds__(256) void qproj_ln_kernel(
    const float* __restrict__ hs, const float* __restrict__ Wk,
    const float* __restrict__ bk, const float* __restrict__ lnw,
    const float* __restrict__ lnb)
{
    __shared__ float As[32][16];
    __shared__ float Bs[16][256];
    const int tid = threadIdx.x;
    const int ty = tid >> 5;      // warp 0..7 -> rows ty*4..+3
    const int tx = tid & 31;      // lane -> cols tx*8..+7
    const int m0 = blockIdx.x * 32;

    ull c2[4][4];
#pragma unroll
    for (int i = 0; i < 4; i++)
#pragma unroll
        for (int j = 0; j < 4; j++) c2[i][j] = 0ull;

    for (int k0 = 0; k0 < DH; k0 += 16) {
        if (tid < 128) {
            int r = tid >> 2, k4 = tid & 3;
            float4 v = *(const float4*)(hs + (size_t)(m0 + r) * DH + k0 + k4 * 4);
            *(float4*)(&As[r][k4 * 4]) = v;
        }
#pragma unroll
        for (int u = 0; u < 4; u++) {
            int idx4 = tid + u * 256;
            int kk = idx4 >> 6, c4 = idx4 & 63;
            float4 v = *(const float4*)(Wk + (size_t)(k0 + kk) * DK + c4 * 4);
            *(float4*)(&Bs[kk][c4 * 4]) = v;
        }
        __syncthreads();
#pragma unroll
        for (int kk = 0; kk < 16; kk++) {
            ull a2[4];
#pragma unroll
            for (int i = 0; i < 4; i++) a2[i] = dup2(As[ty * 4 + i][kk]);
            const ull* bp = (const ull*)&Bs[kk][tx * 8];
#pragma unroll
            for (int i = 0; i < 4; i++) {
                fma2(c2[i][0], a2[i], bp[0]);
                fma2(c2[i][1], a2[i], bp[1]);
                fma2(c2[i][2], a2[i], bp[2]);
                fma2(c2[i][3], a2[i], bp[3]);
            }
        }
        __syncthreads();
    }

    // unpack to scalars for LN
    float c[4][8];
#pragma unroll
    for (int i = 0; i < 4; i++)
#pragma unroll
        for (int j = 0; j < 4; j++) {
            float2 f = *(float2*)&c2[i][j];
            c[i][2 * j] = f.x; c[i][2 * j + 1] = f.y;
        }

    float bkv[8], lw[8], lb[8];
#pragma unroll
    for (int j = 0; j < 8; j++) {
        int col = tx * 8 + j;
        bkv[j] = bk[col]; lw[j] = lnw[col]; lb[j] = lnb[col];
    }
#pragma unroll
    for (int i = 0; i < 4; i++)
#pragma unroll
        for (int j = 0; j < 8; j++) c[i][j] += bkv[j];

#pragma unroll
    for (int i = 0; i < 4; i++) {
        float s = 0.f;
#pragma unroll
        for (int j = 0; j < 8; j++) s += c[i][j];
#pragma unroll
        for (int o = 16; o > 0; o >>= 1) s += __shfl_xor_sync(0xffffffffu, s, o);
        float mu = s * (1.0f / 256.0f);
        float v = 0.f;
#pragma unroll
        for (int j = 0; j < 8; j++) { float d = c[i][j] - mu; v += d * d; }
#pragma unroll
        for (int o = 16; o > 0; o >>= 1) v += __shfl_xor_sync(0xffffffffu, v, o);
        float rs = rsqrtf(v * (1.0f / 256.0f) + 1e-5f);
        float out[8];
#pragma unroll
        for (int j = 0; j < 8; j++)
            out[j] = ((c[i][j] - mu) * rs * lw[j] + lb[j]) * 0.0625f;
        __half* dst = g_qh + (size_t)(m0 + ty * 4 + i) * DK + tx * 8;
        *(uint4*)dst = make_uint4(packh2(out[0], out[1]), packh2(out[2], out[3]),
                                  packh2(out[4], out[5]), packh2(out[6], out[7]));
    }
}

// ---------------------------------------------------------------------------
// Kernel P (fused prep): role by blockIdx.x.
//   [0, KH_BLOCKS)         : keys fp32 -> fp16 (natural layout)
//   [KH_BLOCKS, +VTH_BLOCKS): per-block V transpose -> fp16 [b][d][key]
// ---------------------------------------------------------------------------
#define KH_BLOCKS  ((NBLK * CAP * DK) / (256 * 8))   /* 4096 */
#define VTH_BLOCKS ((DK / 32) * (CAP / 32) * NBLK)   /* 8192 */

__global__ __launch_bounds__(256) void prep_kernel(
    const float* __restrict__ mk, const float* __restrict__ mv)
{
    __shared__ float t[32][33];
    const int bx = blockIdx.x;
    if (bx < KH_BLOCKS) {
        size_t i = ((size_t)bx * 256 + threadIdx.x) * 8;
        float4 v0 = *(const float4*)(mk + i);
        float4 v1 = *(const float4*)(mk + i + 4);
        *(uint4*)(g_kh + i) = make_uint4(packh2(v0.x, v0.y), packh2(v0.z, v0.w),
                                         packh2(v1.x, v1.y), packh2(v1.z, v1.w));
    } else {
        int idx = bx - KH_BLOCKS;
        const int dt = idx & 7;            // DK/32 = 8
        const int kt = (idx >> 3) & 31;    // CAP/32 = 32
        const int b  = idx >> 8;           // NBLK
        const int r = threadIdx.x >> 3, c4 = (threadIdx.x & 7) * 4;
        float4 v = *(const float4*)(mv + ((size_t)b * CAP + kt * 32 + r) * DK + dt * 32 + c4);
        t[r][c4] = v.x; t[r][c4 + 1] = v.y; t[r][c4 + 2] = v.z; t[r][c4 + 3] = v.w;
        __syncthreads();
        uint2 o = make_uint2(packh2(t[c4][r], t[c4 + 1][r]),
                             packh2(t[c4 + 2][r], t[c4 + 3][r]));
        *(uint2*)(g_vth + ((size_t)b * DK + dt * 32 + r) * CAP + kt * 32 + c4) = o;
    }
}

// ---------------------------------------------------------------------------
// Kernel B: per-block masked softmax attention. fp16 mma + ldmatrix,
// chunk = 64 keys, double-buffered cp.async, 256 threads (8 warps) — R10 best.
// CTA = 64 queries x 4 memory blocks (grid 128 x 8) for wave balance.
// QK: warp w -> m16 tile (w>>1), key-half n32 (w&1); 4 mma chains.
// PV: warp w -> m32 group (w&1), col group n64 (w>>1); k=64.
// ---------------------------------------------------------------------------
#define QSTR 264
#define KSTR 264
#define VSTR 72
#define PSTR 72
#define KBUF (64 * KSTR)     /* halves per K buffer  */
#define VBUF (256 * VSTR)    /* halves per Vt buffer */
#define ATTN_SMEM (512 + 64*QSTR*2 + 2*KBUF*2 + 2*VBUF*2 + 64*PSTR*2)

extern __shared__ char sm_raw[];

__global__ __launch_bounds__(256, 1) void attn_kernel(const int* __restrict__ usage)
{
    float*  Ls  = (float*)sm_raw;                 // [64][2]
    __half* Qs  = (__half*)(sm_raw + 512);        // [64][264]
    __half* Ks  = Qs + 64 * QSTR;                 // 2 x [64][264]
    __half* Vts = Ks + 2 * KBUF;                  // 2 x [256][72]
    __half* Ps  = Vts + 2 * VBUF;                 // [64][72]

    const u32 ks_u = s2u(Ks);
    const u32 vt_u = s2u(Vts);

    const int tid  = threadIdx.x;
    const int w    = tid >> 5;
    const int lane = tid & 31;
    const int t4   = lane >> 2;
    const int tq   = lane & 3;
    const int q0   = blockIdx.x * 64;
    const int b0   = blockIdx.y * (NBLK / NPART);

    const int mw = w >> 1;          // QK m16 tile
    const int nh = w & 1;           // QK key-half (n32)
    const int mg = w & 1;           // PV m32 group
    const int ng = w >> 1;          // PV n64 group

    const int l15 = lane & 15, lh = lane >> 4;
    const u32 qa  = s2u(Qs) + (u32)(((mw * 16 + l15) * QSTR + lh * 8) * 2);
    const u32 kb0 = (u32)(((nh * 32 + l15) * KSTR + lh * 8) * 2);        // + ks_u + buf
    const u32 kb1 = kb0 + 16 * KSTR * 2;
    const u32 pa0 = s2u(Ps) + (u32)(((mg * 32 + l15) * PSTR + lh * 8) * 2);
    const u32 pa1 = pa0 + 16 * PSTR * 2;
    const u32 vb0 = (u32)(((ng * 64 + l15) * VSTR + lh * 8) * 2);        // + vt_u + buf

    // Q tile -> smem (once)
#pragma unroll
    for (int u = 0; u < 8; u++) {
        int idx = tid + u * 256;
        int row = idx >> 5, seg = idx & 31;
        uint4 v = *(const uint4*)(g_qh + ((size_t)(q0 + row) << 8) + seg * 8);
        *(uint4*)(Qs + row * QSTR + seg * 8) = v;
    }

    float O[2][8][4];
#pragma unroll
    for (int mt = 0; mt < 2; mt++)
#pragma unroll
        for (int nt = 0; nt < 8; nt++)
#pragma unroll
            for (int j = 0; j < 4; j++) O[mt][nt][j] = 0.f;

    // prefetch chunk 0 of block b0 into buffer 0
    {
        const __half* kg = g_kh + (size_t)b0 * CAP * DK;
        const __half* vg = g_vth + (size_t)b0 * DK * CAP;
#pragma unroll
        for (int u = 0; u < 8; u++) {
            int idx = tid + u * 256;
            int key = idx >> 5, seg = idx & 31;
            cpa16(ks_u + (key * KSTR + seg * 8) * 2, kg + (size_t)key * DK + seg * 8);
            int d = idx >> 3, sg = idx & 7;
            cpa16(vt_u + (d * VSTR + sg * 8) * 2, vg + (size_t)d * CAP + sg * 8);
        }
        CPA_COMMIT();
    }

    int it = 0;
    for (int bb = 0; bb < NBLK / NPART; bb++) {
        const int b = b0 + bb;
        const int use = __ldg(usage + b);
        const int nch = (use + 63) >> 6;

        float acc[2][8][4];
#pragma unroll
        for (int mt = 0; mt < 2; mt++)
#pragma unroll
            for (int nt = 0; nt < 8; nt++)
#pragma unroll
                for (int j = 0; j < 4; j++) acc[mt][nt][j] = 0.f;

        for (int ch = 0; ch < nch; ch++, it++) {
            const int buf = it & 1;
            const int c0 = ch * 64;

            __syncthreads();   // A: prev PV done -> buf^1 free; prev P/Ls consumed

            // prefetch next chunk (possibly next block) into buf^1
            {
                int nb = b, nc = c0 + 64;
                bool has = true;
                if (ch + 1 >= nch) {
                    if (bb + 1 < NBLK / NPART) { nb = b + 1; nc = 0; }
                    else has = false;
                }
                if (has) {
                    const int pb = buf ^ 1;
                    const __half* kg = g_kh + ((size_t)nb * CAP + nc) * DK;
                    const __half* vg = g_vth + (size_t)nb * DK * CAP + nc;
                    const u32 kd = ks_u + pb * KBUF * 2;
                    const u32 vd = vt_u + pb * VBUF * 2;
#pragma unroll
                    for (int u = 0; u < 8; u++) {
                        int idx = tid + u * 256;
                        int key = idx >> 5, seg = idx & 31;
                        cpa16(kd + (key * KSTR + seg * 8) * 2,
                              kg + (size_t)key * DK + seg * 8);
                        int d = idx >> 3, sg = idx & 7;
                        cpa16(vd + (d * VSTR + sg * 8) * 2,
                              vg + (size_t)d * CAP + sg * 8);
                    }
                }
                CPA_COMMIT();
                CPA_WAIT1();   // current chunk's group complete
            }
            __syncthreads();   // B: chunk data visible to all warps

            // ---- S = Q K^T : m16 x n32 over k=256, 4 chains ----
            const u32 kbase = ks_u + buf * KBUF * 2;
            float s[4][4];
#pragma unroll
            for (int nt = 0; nt < 4; nt++)
#pragma unroll
                for (int j = 0; j < 4; j++) s[nt][j] = 0.f;
#pragma unroll
            for (int kk = 0; kk < 16; kk++) {
                u32 A[4], B0[4], B1[4];
                LDSM4(A, qa + kk * 32);
                LDSM4(B0, kbase + kb0 + kk * 32);
                LDSM4(B1, kbase + kb1 + kk * 32);
                mma_f16(s[0], A[0], A[1], A[2], A[3], B0[0], B0[2]);
                mma_f16(s[1], A[0], A[1], A[2], A[3], B0[1], B0[3]);
                mma_f16(s[2], A[0], A[1], A[2], A[3], B1[0], B1[2]);
                mma_f16(s[3], A[0], A[1], A[2], A[3], B1[1], B1[3]);
            }

            // ---- mask + exp + store P + row-sum partials ----
            const int rem = use - c0;   // >= 1
            const int row = mw * 16 + t4;
            float rs_lo = 0.f, rs_hi = 0.f;
#pragma unroll
            for (int nt = 0; nt < 4; nt++) {
                int col = nh * 32 + nt * 8 + 2 * tq;
                float p0 = (col     < rem) ? __expf(s[nt][0]) : 0.f;
                float p1 = (col + 1 < rem) ? __expf(s[nt][1]) : 0.f;
                float p2 = (col     < rem) ? __expf(s[nt][2]) : 0.f;
                float p3 = (col + 1 < rem) ? __expf(s[nt][3]) : 0.f;
                rs_lo += p0 + p1;
                rs_hi += p2 + p3;
                *(u32*)(Ps + row * PSTR + col)       = packh2(p0, p1);
                *(u32*)(Ps + (row + 8) * PSTR + col) = packh2(p2, p3);
            }
            rs_lo += __shfl_xor_sync(0xffffffffu, rs_lo, 1);
            rs_lo += __shfl_xor_sync(0xffffffffu, rs_lo, 2);
            rs_hi += __shfl_xor_sync(0xffffffffu, rs_hi, 1);
            rs_hi += __shfl_xor_sync(0xffffffffu, rs_hi, 2);
            if (tq == 0) {   // unique writer per (row, key-half)
                if (ch == 0) {
                    Ls[row * 2 + nh]       = rs_lo;
                    Ls[(row + 8) * 2 + nh] = rs_hi;
                } else {
                    Ls[row * 2 + nh]       += rs_lo;
                    Ls[(row + 8) * 2 + nh] += rs_hi;
                }
            }
            __syncthreads();   // C: P + Ls visible

            // ---- acc += P @ V : m32 x n64 over k=64 ----
            const u32 vbase = vt_u + buf * VBUF * 2;
#pragma unroll
            for (int kk = 0; kk < 4; kk++) {
                u32 A0[4], A1[4];
                LDSM4(A0, pa0 + kk * 32);
                LDSM4(A1, pa1 + kk * 32);
#pragma unroll
                for (int nt = 0; nt < 4; nt++) {
                    u32 B[4];
                    LDSM4(B, vbase + vb0 + nt * 16 * VSTR * 2 + kk * 32);
                    mma_f16(acc[0][2 * nt],     A0[0], A0[1], A0[2], A0[3], B[0], B[2]);
                    mma_f16(acc[0][2 * nt + 1], A0[0], A0[1], A0[2], A0[3], B[1], B[3]);
                    mma_f16(acc[1][2 * nt],     A1[0], A1[1], A1[2], A1[3], B[0], B[2]);
                    mma_f16(acc[1][2 * nt + 1], A1[0], A1[1], A1[2], A1[3], B[1], B[3]);
                }
            }
        }

        // ---- finalize block: O += acc / rowsum ----
#pragma unroll
        for (int mt = 0; mt < 2; mt++) {
            int r = mg * 32 + mt * 16 + t4;
            float il = 1.0f / (Ls[r * 2] + Ls[r * 2 + 1]);
            float ih = 1.0f / (Ls[(r + 8) * 2] + Ls[(r + 8) * 2 + 1]);
#pragma unroll
            for (int nt = 0; nt < 8; nt++) {
                O[mt][nt][0] += acc[mt][nt][0] * il;
                O[mt][nt][1] += acc[mt][nt][1] * il;
                O[mt][nt][2] += acc[mt][nt][2] * ih;
                O[mt][nt][3] += acc[mt][nt][3] * ih;
            }
        }
    }

    // write partial retrieved values for this block group
    float* dst = g_r + (size_t)blockIdx.y * NQ * DK;
#pragma unroll
    for (int mt = 0; mt < 2; mt++) {
        int r = q0 + mg * 32 + mt * 16 + t4;
#pragma unroll
        for (int nt = 0; nt < 8; nt++) {
            int col = ng * 64 + nt * 8 + 2 * tq;
            *(float2*)(dst + (size_t)r * DK + col) =
                make_float2(O[mt][nt][0], O[mt][nt][1]);
            *(float2*)(dst + (size_t)(r + 8) * DK + col) =
                make_float2(O[mt][nt][2], O[mt][nt][3]);
        }
    }
}

// ---------------------------------------------------------------------------
// Kernel R: reduce NPART partials -> g_rs
// ---------------------------------------------------------------------------
__global__ __launch_bounds__(256) void reduce_r_kernel()
{
    size_t i = ((size_t)blockIdx.x * 256 + threadIdx.x) * 4;
    float4 a = *(const float4*)(g_r + i);
#pragma unroll
    for (int p = 1; p < NPART; p++) {
        float4 b = *(const float4*)(g_r + (size_t)p * NQ * DK + i);
        a.x += b.x; a.y += b.y; a.z += b.z; a.w += b.w;
    }
    *(float4*)(g_rs + i) = a;
}

// ---------------------------------------------------------------------------
// Kernel C: out = g_rs @ Wo + bo   [8192,256]x[256,768], f32x2 packed FMA.
// ---------------------------------------------------------------------------
__global__ __launch_bounds__(256) void out_gemm_kernel(
    const float* __restrict__ Wo, const float* __restrict__ bo,
    float* __restrict__ out)
{
    __shared__ float As[64][20];
    __shared__ float Bs[16][64];
    const int tid = threadIdx.x;
    const int ty = tid >> 4;      // 0..15 -> rows ty*4..+3
    const int tx = tid & 15;      // cols tx*4..+3
    const int m0 = blockIdx.x * 64;
    const int n0 = blockIdx.y * 64;

    ull c2[4][2];
#pragma unroll
    for (int i = 0; i < 4; i++) { c2[i][0] = 0ull; c2[i][1] = 0ull; }

    for (int k0 = 0; k0 < DK; k0 += 16) {
        {
            int r = tid >> 2, k4 = tid & 3;
            float4 v = *(const float4*)(g_rs + (size_t)(m0 + r) * DK + k0 + k4 * 4);
            *(float4*)(&As[r][k4 * 4]) = v;
        }
        {
            int kk = tid >> 4, c4 = tid & 15;
            float4 v = *(const float4*)(Wo + (size_t)(k0 + kk) * DH + n0 + c4 * 4);
            *(float4*)(&Bs[kk][c4 * 4]) = v;
        }
        __syncthreads();
#pragma unroll
        for (int kk = 0; kk < 16; kk++) {
            ull a2[4];
#pragma unroll
            for (int i = 0; i < 4; i++) a2[i] = dup2(As[ty * 4 + i][kk]);
            const ull* bp = (const ull*)&Bs[kk][tx * 4];
#pragma unroll
            for (int i = 0; i < 4; i++) {
                fma2(c2[i][0], a2[i], bp[0]);
                fma2(c2[i][1], a2[i], bp[1]);
            }
        }
        __syncthreads();
    }

    float4 bv = *(const float4*)(bo + n0 + tx * 4);
#pragma unroll
    for (int i = 0; i < 4; i++) {
        float2 f0 = *(float2*)&c2[i][0];
        float2 f1 = *(float2*)&c2[i][1];
        float4 r = make_float4(f0.x + bv.x, f0.y + bv.y, f1.x + bv.z, f1.y + bv.w);
        *(float4*)(out + (size_t)(m0 + ty * 4 + i) * DH + n0 + tx * 4) = r;
    }
}

// ---------------------------------------------------------------------------
extern "C" void kernel_launch(void* const* d_in, const int* in_sizes, int n_in,
                              void* d_out, int out_size)
{
    const float* hs  = (const float*)d_in[0];
    const float* Wk  = (const float*)d_in[1];
    const float* bk  = (const float*)d_in[2];
    const float* lnw = (const float*)d_in[3];
    const float* lnb = (const float*)d_in[4];
    const float* mk  = (const float*)d_in[5];
    const float* mv  = (const float*)d_in[6];
    const float* Wo  = (const float*)d_in[7];
    const float* bo  = (const float*)d_in[8];
    const int* usage = (const int*)d_in[9];
    float* out = (float*)d_out;

    cudaFuncSetAttribute(attn_kernel, cudaFuncAttributeMaxDynamicSharedMemorySize,
                         ATTN_SMEM);

    qproj_ln_kernel<<<NQ / 32, 256>>>(hs, Wk, bk, lnw, lnb);
    prep_kernel<<<KH_BLOCKS + VTH_BLOCKS, 256>>>(mk, mv);
    attn_kernel<<<dim3(NQ / 64, NPART), 256, ATTN_SMEM>>>(usage);
    reduce_r_kernel<<<(NQ * DK) / (256 * 4), 256>>>();
    dim3 gc(NQ / 64, DH / 64);
    out_gemm_kernel<<<gc, 256>>>(Wo, bo, out);
}